// round 2
// baseline (speedup 1.0000x reference)
#include <cuda_runtime.h>
#include <math.h>

#define N_NODES 10000
#define N_EDGES 160000
#define RCUT 1.4415f

// Scratch (allocations forbidden; device globals allowed)
__device__ __align__(16) float g_sj[(size_t)N_NODES * 384];   // phase-1 per-node features
__device__ __align__(16) float g_msg2[(size_t)N_NODES * 512]; // phase-2 per-node message

__device__ __forceinline__ float silu_f(float v) { return v / (1.0f + __expf(-v)); }

__device__ __forceinline__ void red4(float* p, float a, float b, float c, float d) {
    asm volatile("red.global.add.v4.f32 [%0], {%1,%2,%3,%4};"
                 :: "l"(p), "f"(a), "f"(b), "f"(c), "f"(d) : "memory");
}

// ---------------------------------------------------------------------------
// Kernel A: per-node  g_sj = silu(x[:,384:] @ W1 + b1) @ W3 + b3
// 16 nodes/block, 256 threads (2 groups x 128).
// ---------------------------------------------------------------------------
__global__ __launch_bounds__(256) void kA(const float* __restrict__ x,
                                          const float* __restrict__ W1,
                                          const float* __restrict__ b1,
                                          const float* __restrict__ W3,
                                          const float* __restrict__ b3) {
    __shared__ float s_in[16][128];
    __shared__ float t[16][128];
    const int tid = threadIdx.x;
    const int nb  = blockIdx.x * 16;

    for (int idx = tid; idx < 16 * 128; idx += 256) {
        int m = idx >> 7, c = idx & 127;
        s_in[m][c] = x[(size_t)(nb + m) * 512 + 384 + c];
    }
    __syncthreads();

    const int g = tid >> 7;      // 0..1 (8 nodes each)
    const int o = tid & 127;     // output column

    // GEMM1: t = silu(s_in @ W1 + b1)
    float acc[8];
    {
        float bb = b1[o];
#pragma unroll
        for (int j = 0; j < 8; j++) acc[j] = bb;
        for (int k = 0; k < 128; k++) {
            float w = W1[k * 128 + o];
#pragma unroll
            for (int j = 0; j < 8; j++) acc[j] += s_in[g * 8 + j][k] * w;
        }
#pragma unroll
        for (int j = 0; j < 8; j++) t[g * 8 + j][o] = silu_f(acc[j]);
    }
    __syncthreads();

    // GEMM2: sj = t @ W3 + b3  (N=384, three column slabs per thread)
    float a2[8][3];
#pragma unroll
    for (int p = 0; p < 3; p++) {
        float bv = b3[o + 128 * p];
#pragma unroll
        for (int j = 0; j < 8; j++) a2[j][p] = bv;
    }
    for (int k = 0; k < 128; k++) {
        float w0 = W3[k * 384 + o];
        float w1 = W3[k * 384 + o + 128];
        float w2 = W3[k * 384 + o + 256];
#pragma unroll
        for (int j = 0; j < 8; j++) {
            float tv = t[g * 8 + j][k];
            a2[j][0] += tv * w0;
            a2[j][1] += tv * w1;
            a2[j][2] += tv * w2;
        }
    }
#pragma unroll
    for (int j = 0; j < 8; j++) {
        size_t base = (size_t)(nb + g * 8 + j) * 384;
#pragma unroll
        for (int p = 0; p < 3; p++) g_sj[base + o + 128 * p] = a2[j][p];
    }
}

// ---------------------------------------------------------------------------
// Kernel B: per-edge phase-1 message + scatter.
// 8 edges/block, 256 threads (2 groups x 128, 4 edges per group).
// ---------------------------------------------------------------------------
__global__ __launch_bounds__(256) void kB(const float* __restrict__ x,
                                          const int* __restrict__ ei,
                                          const float* __restrict__ ea1,
                                          const float* __restrict__ ea2,
                                          const float* __restrict__ W2,
                                          const float* __restrict__ b2,
                                          float* __restrict__ out) {
    __shared__ float w2s[20 * 384];      // 30 KB
    __shared__ float split[8][384];      // 12 KB
    __shared__ float rbfc[8][20];
    __shared__ float ea[8][3];
    __shared__ int   srcs[8], dsts[8];

    const int tid = threadIdx.x;
    const int e0  = blockIdx.x * 8;

    for (int i = tid; i < 20 * 384; i += 256) w2s[i] = W2[i];
    if (tid < 8) {
        srcs[tid] = ei[e0 + tid];
        dsts[tid] = ei[N_EDGES + e0 + tid];
    }
    if (tid >= 8 && tid < 32) {
        int q = tid - 8;
        int e = q / 3, k = q % 3;
        ea[e][k] = ea1[(size_t)(e0 + e) * 3 + k];
    }
    if (tid >= 64 && tid < 224) {   // 8 edges x 20 rbf terms
        int q = tid - 64;
        int e = q / 20, n = q % 20;
        float r  = ea2[e0 + e];
        float rb = sqrtf(2.0f / RCUT) * sinpif((float)(n + 1) * r / RCUT) / r;
        float co = 0.5f * (cospif(r / RCUT) + 1.0f) * (r < RCUT ? 1.0f : 0.0f);
        rbfc[e][n] = rb * co;
    }
    __syncthreads();

    const int g = tid >> 7;
    const int o = tid & 127;

    // split = s_j[src] * (rbfc @ W2 + b2)
#pragma unroll
    for (int el = 0; el < 4; el++) {
        int e = g * 4 + el;
        float a0 = b2[o], a1 = b2[o + 128], a2v = b2[o + 256];
#pragma unroll
        for (int n = 0; n < 20; n++) {
            float rn = rbfc[e][n];
            a0  += rn * w2s[n * 384 + o];
            a1  += rn * w2s[n * 384 + o + 128];
            a2v += rn * w2s[n * 384 + o + 256];
        }
        const float* sjr = g_sj + (size_t)srcs[e] * 384;
        split[e][o]       = a0  * sjr[o];
        split[e][o + 128] = a1  * sjr[o + 128];
        split[e][o + 256] = a2v * sjr[o + 256];
    }
    __syncthreads();

    // msg[3i+k] = x[src,3i+k]*s1[i] + s3[i]*ea1[k] ;  msg[384+i] = s2[i]
#pragma unroll
    for (int el = 0; el < 4; el++) {
        int e   = g * 4 + el;
        int src = srcs[e], dst = dsts[e];
        float v0, v1, v2, v3;
        if (o < 96) {
            int j0 = 4 * o;
            const float4 xv = *(const float4*)(x + (size_t)src * 512 + j0);
            float xs[4] = {xv.x, xv.y, xv.z, xv.w};
            float vals[4];
#pragma unroll
            for (int tq = 0; tq < 4; tq++) {
                int j = j0 + tq;
                int i = j / 3;
                int k = j - 3 * i;
                vals[tq] = xs[tq] * split[e][i] + split[e][256 + i] * ea[e][k];
            }
            v0 = vals[0]; v1 = vals[1]; v2 = vals[2]; v3 = vals[3];
        } else {
            int i0 = 4 * (o - 96);
            v0 = split[e][128 + i0];
            v1 = split[e][128 + i0 + 1];
            v2 = split[e][128 + i0 + 2];
            v3 = split[e][128 + i0 + 3];
        }
        red4(out + (size_t)dst * 512 + 4 * o, v0, v1, v2, v3);
    }
}

// ---------------------------------------------------------------------------
// Kernel C: per-node phase-2 message into g_msg2. 8 nodes/block, 256 threads.
// Static smem = 48 KB exactly.
// ---------------------------------------------------------------------------
__global__ __launch_bounds__(256) void kC(const float* __restrict__ xmid,
                                          const float* __restrict__ U,
                                          const float* __restrict__ V,
                                          const float* __restrict__ Wu1,
                                          const float* __restrict__ bu1,
                                          const float* __restrict__ Wu2,
                                          const float* __restrict__ bu2) {
    __shared__ float vA[8][384];   // v, later overwritten by vV
    __shared__ float vUs[8][384];  // v @ U
    __shared__ float ns[8][256];   // [norm | s]
    __shared__ float h1[8][128];
    __shared__ float h[8][384];

    const int tid = threadIdx.x;
    const int nb  = blockIdx.x * 8;

    for (int idx = tid; idx < 8 * 384; idx += 256) {
        int m = idx / 384, j = idx % 384;
        vA[m][j] = xmid[(size_t)(nb + m) * 512 + j];
    }
    for (int idx = tid; idx < 8 * 128; idx += 256) {
        int m = idx >> 7, i = idx & 127;
        ns[m][128 + i] = xmid[(size_t)(nb + m) * 512 + 384 + i];
    }
    __syncthreads();

    const int g = tid >> 7;   // 0..1 (4 nodes each)
    const int o = tid & 127;

    // vU = v @ U   (v in (3,128) row-major layout: v[a,k] = vA[m][a*128+k])
    {
        float acc[4][3];
#pragma unroll
        for (int j = 0; j < 4; j++)
#pragma unroll
            for (int a = 0; a < 3; a++) acc[j][a] = 0.0f;
        for (int k = 0; k < 128; k++) {
            float u = U[k * 128 + o];
#pragma unroll
            for (int j = 0; j < 4; j++) {
                int m = g * 4 + j;
                acc[j][0] += vA[m][k] * u;
                acc[j][1] += vA[m][128 + k] * u;
                acc[j][2] += vA[m][256 + k] * u;
            }
        }
#pragma unroll
        for (int j = 0; j < 4; j++)
#pragma unroll
            for (int a = 0; a < 3; a++) vUs[g * 4 + j][a * 128 + o] = acc[j][a];
    }
    __syncthreads();

    // vV = vU @ V  -> overwrite vA (v no longer needed)
    {
        float acc[4][3];
#pragma unroll
        for (int j = 0; j < 4; j++)
#pragma unroll
            for (int a = 0; a < 3; a++) acc[j][a] = 0.0f;
        for (int k = 0; k < 128; k++) {
            float vv = V[k * 128 + o];
#pragma unroll
            for (int j = 0; j < 4; j++) {
                int m = g * 4 + j;
                acc[j][0] += vUs[m][k] * vv;
                acc[j][1] += vUs[m][128 + k] * vv;
                acc[j][2] += vUs[m][256 + k] * vv;
            }
        }
        __syncthreads();
#pragma unroll
        for (int j = 0; j < 4; j++)
#pragma unroll
            for (int a = 0; a < 3; a++) vA[g * 4 + j][a * 128 + o] = acc[j][a];
    }
    __syncthreads();

    // norms: reshaped index (i,k) -> flat 3i+k
    for (int idx = tid; idx < 8 * 128; idx += 256) {
        int m = idx >> 7, i = idx & 127;
        float x0 = vA[m][3 * i], x1 = vA[m][3 * i + 1], x2 = vA[m][3 * i + 2];
        ns[m][i] = sqrtf(x0 * x0 + x1 * x1 + x2 * x2);
    }
    __syncthreads();

    // h1 = silu([norm|s] @ Wu1 + bu1)
    {
        float acc[4];
        float bv = bu1[o];
#pragma unroll
        for (int j = 0; j < 4; j++) acc[j] = bv;
        for (int k = 0; k < 256; k++) {
            float w = Wu1[k * 128 + o];
#pragma unroll
            for (int j = 0; j < 4; j++) acc[j] += ns[g * 4 + j][k] * w;
        }
#pragma unroll
        for (int j = 0; j < 4; j++) h1[g * 4 + j][o] = silu_f(acc[j]);
    }
    __syncthreads();

    // h = h1 @ Wu2 + bu2
    {
        float acc[4][3];
#pragma unroll
        for (int p = 0; p < 3; p++) {
            float bv = bu2[o + 128 * p];
#pragma unroll
            for (int j = 0; j < 4; j++) acc[j][p] = bv;
        }
        for (int k = 0; k < 128; k++) {
            float w0 = Wu2[k * 384 + o];
            float w1 = Wu2[k * 384 + o + 128];
            float w2 = Wu2[k * 384 + o + 256];
#pragma unroll
            for (int j = 0; j < 4; j++) {
                float tv = h1[g * 4 + j][k];
                acc[j][0] += tv * w0;
                acc[j][1] += tv * w1;
                acc[j][2] += tv * w2;
            }
        }
#pragma unroll
        for (int j = 0; j < 4; j++)
#pragma unroll
            for (int p = 0; p < 3; p++) h[g * 4 + j][o + 128 * p] = acc[j][p];
    }
    __syncthreads();

    // msg2[j<384]   = vU_flat[j] * s1[j/3]
    // msg2[384+i]   = s1[i] * sum_k vU[3i+k]*vV[3i+k] + s3[i]
    for (int idx = tid; idx < 8 * 512; idx += 256) {
        int m = idx >> 9, j = idx & 511;
        float val;
        if (j < 384) {
            val = vUs[m][j] * h[m][j / 3];
        } else {
            int i = j - 384;
            float d = vUs[m][3 * i]     * vA[m][3 * i]
                    + vUs[m][3 * i + 1] * vA[m][3 * i + 1]
                    + vUs[m][3 * i + 2] * vA[m][3 * i + 2];
            val = d * h[m][i] + h[m][256 + i];
        }
        g_msg2[(size_t)(nb + m) * 512 + j] = val;
    }
}

// ---------------------------------------------------------------------------
// Kernel D: per-edge scatter of the per-node phase-2 message.
// 2 edges/block, 256 threads.
// ---------------------------------------------------------------------------
__global__ __launch_bounds__(256) void kD(const int* __restrict__ ei,
                                          float* __restrict__ out) {
    const int tid = threadIdx.x;
    const int g = tid >> 7, o = tid & 127;
    const int e = blockIdx.x * 2 + g;
    const int src = ei[e];
    const int dst = ei[N_EDGES + e];
    const float4 v = *(const float4*)(g_msg2 + (size_t)src * 512 + 4 * o);
    red4(out + (size_t)dst * 512 + 4 * o, v.x, v.y, v.z, v.w);
}

// ---------------------------------------------------------------------------
extern "C" void kernel_launch(void* const* d_in, const int* in_sizes, int n_in,
                              void* d_out, int out_size) {
    const float* x   = (const float*)d_in[0];
    const int*   ei  = (const int*)d_in[1];     // int32! (jax x64 disabled)
    const float* ea1 = (const float*)d_in[2];
    const float* ea2 = (const float*)d_in[3];
    const float* W1  = (const float*)d_in[4];
    const float* b1  = (const float*)d_in[5];
    const float* W2  = (const float*)d_in[6];
    const float* b2  = (const float*)d_in[7];
    const float* W3  = (const float*)d_in[8];
    const float* b3  = (const float*)d_in[9];
    const float* U   = (const float*)d_in[10];
    const float* V   = (const float*)d_in[11];
    const float* Wu1 = (const float*)d_in[12];
    const float* bu1 = (const float*)d_in[13];
    const float* Wu2 = (const float*)d_in[14];
    const float* bu2 = (const float*)d_in[15];
    float* out = (float*)d_out;

    cudaMemcpyAsync(out, x, (size_t)N_NODES * 512 * sizeof(float),
                    cudaMemcpyDeviceToDevice);

    kA<<<N_NODES / 16, 256>>>(x, W1, b1, W3, b3);
    kB<<<N_EDGES / 8, 256>>>(x, ei, ea1, ea2, W2, b2, out);
    kC<<<N_NODES / 8, 256>>>(out, U, V, Wu1, bu1, Wu2, bu2);
    kD<<<N_EDGES / 2, 256>>>(ei, out);
}

// round 3
// speedup vs baseline: 1.2152x; 1.2152x over previous
#include <cuda_runtime.h>
#include <math.h>

#define N_NODES 10000
#define N_EDGES 160000
#define RCUT 1.4415f

__device__ __align__(16) float g_sj[(size_t)N_NODES * 384];   // phase-1 per-node features
__device__ __align__(16) float g_msg2[(size_t)N_NODES * 512]; // phase-2 per-node message

__device__ __forceinline__ float silu_f(float v) { return v / (1.0f + __expf(-v)); }

__device__ __forceinline__ void red4(float* p, float a, float b, float c, float d) {
    asm volatile("red.global.add.v4.f32 [%0], {%1,%2,%3,%4};"
                 :: "l"(p), "f"(a), "f"(b), "f"(c), "f"(d) : "memory");
}

// ---------------------------------------------------------------------------
// Kernel A: per-node  g_sj = silu(x[:,384:] @ W1 + b1) @ W3 + b3
// 16 nodes/block, 256 threads (2 groups x 128). float4 smem loads, k-unroll 4.
// ---------------------------------------------------------------------------
__global__ __launch_bounds__(256) void kA(const float* __restrict__ x,
                                          const float* __restrict__ W1,
                                          const float* __restrict__ b1,
                                          const float* __restrict__ W3,
                                          const float* __restrict__ b3) {
    __shared__ __align__(16) float s_in[16][128];
    __shared__ __align__(16) float t[16][128];
    const int tid = threadIdx.x;
    const int nb  = blockIdx.x * 16;

    for (int idx = tid; idx < 16 * 128; idx += 256) {
        int m = idx >> 7, c = idx & 127;
        s_in[m][c] = x[(size_t)(nb + m) * 512 + 384 + c];
    }
    __syncthreads();

    const int g = tid >> 7;      // 0..1 (8 nodes each)
    const int o = tid & 127;     // output column

    // GEMM1: t = silu(s_in @ W1 + b1)
    {
        float acc[8];
        float bb = b1[o];
#pragma unroll
        for (int j = 0; j < 8; j++) acc[j] = bb;
        for (int k = 0; k < 128; k += 4) {
            float w0 = W1[(k + 0) * 128 + o];
            float w1 = W1[(k + 1) * 128 + o];
            float w2 = W1[(k + 2) * 128 + o];
            float w3 = W1[(k + 3) * 128 + o];
#pragma unroll
            for (int j = 0; j < 8; j++) {
                float4 s = *(const float4*)&s_in[g * 8 + j][k];
                acc[j] += s.x * w0 + s.y * w1 + s.z * w2 + s.w * w3;
            }
        }
#pragma unroll
        for (int j = 0; j < 8; j++) t[g * 8 + j][o] = silu_f(acc[j]);
    }
    __syncthreads();

    // GEMM2: sj = t @ W3 + b3
    float a2[8][3];
#pragma unroll
    for (int p = 0; p < 3; p++) {
        float bv = b3[o + 128 * p];
#pragma unroll
        for (int j = 0; j < 8; j++) a2[j][p] = bv;
    }
    for (int k = 0; k < 128; k += 4) {
        float w[3][4];
#pragma unroll
        for (int q = 0; q < 4; q++) {
            w[0][q] = W3[(k + q) * 384 + o];
            w[1][q] = W3[(k + q) * 384 + o + 128];
            w[2][q] = W3[(k + q) * 384 + o + 256];
        }
#pragma unroll
        for (int j = 0; j < 8; j++) {
            float4 tv = *(const float4*)&t[g * 8 + j][k];
#pragma unroll
            for (int p = 0; p < 3; p++)
                a2[j][p] += tv.x * w[p][0] + tv.y * w[p][1] + tv.z * w[p][2] + tv.w * w[p][3];
        }
    }
#pragma unroll
    for (int j = 0; j < 8; j++) {
        size_t base = (size_t)(nb + g * 8 + j) * 384;
#pragma unroll
        for (int p = 0; p < 3; p++) g_sj[base + o + 128 * p] = a2[j][p];
    }
}

// ---------------------------------------------------------------------------
// Kernel B: per-edge phase-1 message + scatter.
// 20 edges/block, 256 threads (2 groups x 128, 10 edges per group).
// W2 slice cached in 60 registers per thread (thread-invariant column o).
// ---------------------------------------------------------------------------
__global__ __launch_bounds__(256) void kB(const float* __restrict__ x,
                                          const int* __restrict__ ei,
                                          const float* __restrict__ ea1,
                                          const float* __restrict__ ea2,
                                          const float* __restrict__ W2,
                                          const float* __restrict__ b2,
                                          float* __restrict__ out) {
    __shared__ __align__(16) float split[20][384];   // 30 KB
    __shared__ float rbfc[20][20];
    __shared__ float ea[20][3];
    __shared__ int   srcs[20], dsts[20];

    const int tid = threadIdx.x;
    const int e0  = blockIdx.x * 20;

    if (tid < 20) {
        srcs[tid] = ei[e0 + tid];
        dsts[tid] = ei[N_EDGES + e0 + tid];
    }
    if (tid >= 32 && tid < 92) {
        int q = tid - 32;
        int e = q / 3, k = q % 3;
        ea[e][k] = ea1[(size_t)(e0 + e) * 3 + k];
    }
    for (int q = tid; q < 400; q += 256) {
        int e = q / 20, n = q % 20;
        float r  = ea2[e0 + e];
        float rb = sqrtf(2.0f / RCUT) * sinpif((float)(n + 1) * r / RCUT) / r;
        float co = 0.5f * (cospif(r / RCUT) + 1.0f) * (r < RCUT ? 1.0f : 0.0f);
        rbfc[e][n] = rb * co;
    }

    const int g = tid >> 7;
    const int o = tid & 127;

    // Register-cached W2 slice for this thread's output column
    float w2r0[20], w2r1[20], w2r2[20];
#pragma unroll
    for (int n = 0; n < 20; n++) {
        w2r0[n] = W2[n * 384 + o];
        w2r1[n] = W2[n * 384 + o + 128];
        w2r2[n] = W2[n * 384 + o + 256];
    }
    const float b2v0 = b2[o], b2v1 = b2[o + 128], b2v2 = b2[o + 256];
    __syncthreads();

    // Pass 1: split = s_j[src] * (rbfc @ W2 + b2)
#pragma unroll
    for (int el = 0; el < 10; el++) {
        int e = g * 10 + el;
        float a0 = b2v0, a1 = b2v1, a2v = b2v2;
#pragma unroll
        for (int n = 0; n < 20; n++) {
            float rn = rbfc[e][n];
            a0  += rn * w2r0[n];
            a1  += rn * w2r1[n];
            a2v += rn * w2r2[n];
        }
        const float* sjr = g_sj + (size_t)srcs[e] * 384;
        split[e][o]       = a0  * sjr[o];
        split[e][o + 128] = a1  * sjr[o + 128];
        split[e][o + 256] = a2v * sjr[o + 256];
    }
    __syncthreads();

    // Pass 2: msg[3i+k] = x[src,3i+k]*s1[i] + s3[i]*ea1[k]; msg[384+i] = s2[i]
#pragma unroll
    for (int el = 0; el < 10; el++) {
        int e   = g * 10 + el;
        int src = srcs[e], dst = dsts[e];
        float v0, v1, v2, v3;
        if (o < 96) {
            int j0 = 4 * o;
            const float4 xv = *(const float4*)(x + (size_t)src * 512 + j0);
            float xs[4] = {xv.x, xv.y, xv.z, xv.w};
            float vals[4];
#pragma unroll
            for (int tq = 0; tq < 4; tq++) {
                int j = j0 + tq;
                int i = j / 3;
                int k = j - 3 * i;
                vals[tq] = xs[tq] * split[e][i] + split[e][256 + i] * ea[e][k];
            }
            v0 = vals[0]; v1 = vals[1]; v2 = vals[2]; v3 = vals[3];
        } else {
            int i0 = 4 * (o - 96);
            v0 = split[e][128 + i0];
            v1 = split[e][128 + i0 + 1];
            v2 = split[e][128 + i0 + 2];
            v3 = split[e][128 + i0 + 3];
        }
        red4(out + (size_t)dst * 512 + 4 * o, v0, v1, v2, v3);
    }
}

// ---------------------------------------------------------------------------
// Kernel C: per-node phase-2 message into g_msg2. 8 nodes/block, 256 threads.
// ---------------------------------------------------------------------------
__global__ __launch_bounds__(256) void kC(const float* __restrict__ xmid,
                                          const float* __restrict__ U,
                                          const float* __restrict__ V,
                                          const float* __restrict__ Wu1,
                                          const float* __restrict__ bu1,
                                          const float* __restrict__ Wu2,
                                          const float* __restrict__ bu2) {
    __shared__ __align__(16) float vA[8][384];   // v, later overwritten by vV
    __shared__ __align__(16) float vUs[8][384];  // v @ U
    __shared__ __align__(16) float ns[8][256];   // [norm | s]
    __shared__ __align__(16) float h1[8][128];
    __shared__ __align__(16) float h[8][384];

    const int tid = threadIdx.x;
    const int nb  = blockIdx.x * 8;

    for (int idx = tid; idx < 8 * 384; idx += 256) {
        int m = idx / 384, j = idx % 384;
        vA[m][j] = xmid[(size_t)(nb + m) * 512 + j];
    }
    for (int idx = tid; idx < 8 * 128; idx += 256) {
        int m = idx >> 7, i = idx & 127;
        ns[m][128 + i] = xmid[(size_t)(nb + m) * 512 + 384 + i];
    }
    __syncthreads();

    const int g = tid >> 7;   // 0..1 (4 nodes each)
    const int o = tid & 127;

    // vU = v @ U   (v[a,k] = vA[m][a*128+k])
    {
        float acc[4][3];
#pragma unroll
        for (int j = 0; j < 4; j++)
#pragma unroll
            for (int a = 0; a < 3; a++) acc[j][a] = 0.0f;
        for (int k = 0; k < 128; k += 4) {
            float u0 = U[(k + 0) * 128 + o];
            float u1 = U[(k + 1) * 128 + o];
            float u2 = U[(k + 2) * 128 + o];
            float u3 = U[(k + 3) * 128 + o];
#pragma unroll
            for (int j = 0; j < 4; j++) {
                int m = g * 4 + j;
#pragma unroll
                for (int a = 0; a < 3; a++) {
                    float4 s = *(const float4*)&vA[m][a * 128 + k];
                    acc[j][a] += s.x * u0 + s.y * u1 + s.z * u2 + s.w * u3;
                }
            }
        }
#pragma unroll
        for (int j = 0; j < 4; j++)
#pragma unroll
            for (int a = 0; a < 3; a++) vUs[g * 4 + j][a * 128 + o] = acc[j][a];
    }
    __syncthreads();

    // vV = vU @ V  -> overwrite vA
    {
        float acc[4][3];
#pragma unroll
        for (int j = 0; j < 4; j++)
#pragma unroll
            for (int a = 0; a < 3; a++) acc[j][a] = 0.0f;
        for (int k = 0; k < 128; k += 4) {
            float u0 = V[(k + 0) * 128 + o];
            float u1 = V[(k + 1) * 128 + o];
            float u2 = V[(k + 2) * 128 + o];
            float u3 = V[(k + 3) * 128 + o];
#pragma unroll
            for (int j = 0; j < 4; j++) {
                int m = g * 4 + j;
#pragma unroll
                for (int a = 0; a < 3; a++) {
                    float4 s = *(const float4*)&vUs[m][a * 128 + k];
                    acc[j][a] += s.x * u0 + s.y * u1 + s.z * u2 + s.w * u3;
                }
            }
        }
        __syncthreads();
#pragma unroll
        for (int j = 0; j < 4; j++)
#pragma unroll
            for (int a = 0; a < 3; a++) vA[g * 4 + j][a * 128 + o] = acc[j][a];
    }
    __syncthreads();

    // norms
    for (int idx = tid; idx < 8 * 128; idx += 256) {
        int m = idx >> 7, i = idx & 127;
        float x0 = vA[m][3 * i], x1 = vA[m][3 * i + 1], x2 = vA[m][3 * i + 2];
        ns[m][i] = sqrtf(x0 * x0 + x1 * x1 + x2 * x2);
    }
    __syncthreads();

    // h1 = silu([norm|s] @ Wu1 + bu1)
    {
        float acc[4];
        float bv = bu1[o];
#pragma unroll
        for (int j = 0; j < 4; j++) acc[j] = bv;
        for (int k = 0; k < 256; k += 4) {
            float w0 = Wu1[(k + 0) * 128 + o];
            float w1 = Wu1[(k + 1) * 128 + o];
            float w2 = Wu1[(k + 2) * 128 + o];
            float w3 = Wu1[(k + 3) * 128 + o];
#pragma unroll
            for (int j = 0; j < 4; j++) {
                float4 s = *(const float4*)&ns[g * 4 + j][k];
                acc[j] += s.x * w0 + s.y * w1 + s.z * w2 + s.w * w3;
            }
        }
#pragma unroll
        for (int j = 0; j < 4; j++) h1[g * 4 + j][o] = silu_f(acc[j]);
    }
    __syncthreads();

    // h = h1 @ Wu2 + bu2
    {
        float acc[4][3];
#pragma unroll
        for (int p = 0; p < 3; p++) {
            float bv = bu2[o + 128 * p];
#pragma unroll
            for (int j = 0; j < 4; j++) acc[j][p] = bv;
        }
        for (int k = 0; k < 128; k += 4) {
            float w[3][4];
#pragma unroll
            for (int q = 0; q < 4; q++) {
                w[0][q] = Wu2[(k + q) * 384 + o];
                w[1][q] = Wu2[(k + q) * 384 + o + 128];
                w[2][q] = Wu2[(k + q) * 384 + o + 256];
            }
#pragma unroll
            for (int j = 0; j < 4; j++) {
                float4 tv = *(const float4*)&h1[g * 4 + j][k];
#pragma unroll
                for (int p = 0; p < 3; p++)
                    acc[j][p] += tv.x * w[p][0] + tv.y * w[p][1] + tv.z * w[p][2] + tv.w * w[p][3];
            }
        }
#pragma unroll
        for (int j = 0; j < 4; j++)
#pragma unroll
            for (int p = 0; p < 3; p++) h[g * 4 + j][o + 128 * p] = acc[j][p];
    }
    __syncthreads();

    // msg2
    for (int idx = tid; idx < 8 * 512; idx += 256) {
        int m = idx >> 9, j = idx & 511;
        float val;
        if (j < 384) {
            val = vUs[m][j] * h[m][j / 3];
        } else {
            int i = j - 384;
            float d = vUs[m][3 * i]     * vA[m][3 * i]
                    + vUs[m][3 * i + 1] * vA[m][3 * i + 1]
                    + vUs[m][3 * i + 2] * vA[m][3 * i + 2];
            val = d * h[m][i] + h[m][256 + i];
        }
        g_msg2[(size_t)(nb + m) * 512 + j] = val;
    }
}

// ---------------------------------------------------------------------------
// Kernel D: per-edge scatter of the per-node phase-2 message.
// 4 edges/block, 256 threads, 2 edges per thread (MLP=2).
// ---------------------------------------------------------------------------
__global__ __launch_bounds__(256) void kD(const int* __restrict__ ei,
                                          float* __restrict__ out) {
    const int tid = threadIdx.x;
    const int g = tid >> 7, o = tid & 127;
    const int e0 = blockIdx.x * 4 + g * 2;

    const int src0 = ei[e0],     dst0 = ei[N_EDGES + e0];
    const int src1 = ei[e0 + 1], dst1 = ei[N_EDGES + e0 + 1];
    const float4 v0 = *(const float4*)(g_msg2 + (size_t)src0 * 512 + 4 * o);
    const float4 v1 = *(const float4*)(g_msg2 + (size_t)src1 * 512 + 4 * o);
    red4(out + (size_t)dst0 * 512 + 4 * o, v0.x, v0.y, v0.z, v0.w);
    red4(out + (size_t)dst1 * 512 + 4 * o, v1.x, v1.y, v1.z, v1.w);
}

// ---------------------------------------------------------------------------
extern "C" void kernel_launch(void* const* d_in, const int* in_sizes, int n_in,
                              void* d_out, int out_size) {
    const float* x   = (const float*)d_in[0];
    const int*   ei  = (const int*)d_in[1];     // int32 (jax x64 disabled)
    const float* ea1 = (const float*)d_in[2];
    const float* ea2 = (const float*)d_in[3];
    const float* W1  = (const float*)d_in[4];
    const float* b1  = (const float*)d_in[5];
    const float* W2  = (const float*)d_in[6];
    const float* b2  = (const float*)d_in[7];
    const float* W3  = (const float*)d_in[8];
    const float* b3  = (const float*)d_in[9];
    const float* U   = (const float*)d_in[10];
    const float* V   = (const float*)d_in[11];
    const float* Wu1 = (const float*)d_in[12];
    const float* bu1 = (const float*)d_in[13];
    const float* Wu2 = (const float*)d_in[14];
    const float* bu2 = (const float*)d_in[15];
    float* out = (float*)d_out;

    cudaMemcpyAsync(out, x, (size_t)N_NODES * 512 * sizeof(float),
                    cudaMemcpyDeviceToDevice);

    kA<<<N_NODES / 16, 256>>>(x, W1, b1, W3, b3);
    kB<<<N_EDGES / 20, 256>>>(x, ei, ea1, ea2, W2, b2, out);
    kC<<<N_NODES / 8, 256>>>(out, U, V, Wu1, bu1, Wu2, bu2);
    kD<<<N_EDGES / 4, 256>>>(ei, out);
}

// round 4
// speedup vs baseline: 1.3329x; 1.0969x over previous
#include <cuda_runtime.h>
#include <math.h>

#define N_NODES 10000
#define N_EDGES 160000
#define RCUT 1.4415f

typedef unsigned long long u64;

__device__ __align__(16) float g_sj[(size_t)N_NODES * 384];   // phase-1 per-node features
__device__ __align__(16) float g_msg2[(size_t)N_NODES * 512]; // phase-2 per-node message

__device__ __forceinline__ float silu_f(float v) { return v / (1.0f + __expf(-v)); }

__device__ __forceinline__ void red4(float* p, float a, float b, float c, float d) {
    asm volatile("red.global.add.v4.f32 [%0], {%1,%2,%3,%4};"
                 :: "l"(p), "f"(a), "f"(b), "f"(c), "f"(d) : "memory");
}

// ---- packed f32x2 helpers -------------------------------------------------
__device__ __forceinline__ u64 pk(float x, float y) {
    u64 r; asm("mov.b64 %0, {%1,%2};" : "=l"(r) : "f"(x), "f"(y)); return r;
}
__device__ __forceinline__ u64 f2fma(u64 a, u64 b, u64 c) {
    u64 d; asm("fma.rn.f32x2 %0, %1, %2, %3;" : "=l"(d) : "l"(a), "l"(b), "l"(c)); return d;
}
__device__ __forceinline__ float hsum(u64 a) {
    float lo, hi; asm("mov.b64 {%0,%1}, %2;" : "=f"(lo), "=f"(hi) : "l"(a)); return lo + hi;
}

// ---------------------------------------------------------------------------
// Kernel A: per-node  g_sj = silu(x[:,384:] @ W1 + b1) @ W3 + b3
// 16 nodes/block, 256 threads (2 groups x 128). f32x2 packed FMA.
// ---------------------------------------------------------------------------
__global__ __launch_bounds__(256) void kA(const float* __restrict__ x,
                                          const float* __restrict__ W1,
                                          const float* __restrict__ b1,
                                          const float* __restrict__ W3,
                                          const float* __restrict__ b3) {
    __shared__ __align__(16) float s_in[16][128];
    __shared__ __align__(16) float t[16][128];
    const int tid = threadIdx.x;
    const int nb  = blockIdx.x * 16;

    for (int idx = tid; idx < 16 * 32; idx += 256) {
        int m = idx >> 5, c = (idx & 31) * 4;
        *(float4*)&s_in[m][c] = *(const float4*)(x + (size_t)(nb + m) * 512 + 384 + c);
    }
    __syncthreads();

    const int g = tid >> 7;      // 0..1 (8 nodes each)
    const int o = tid & 127;     // output column

    // GEMM1: t = silu(s_in @ W1 + b1)
    {
        u64 acc[8];
        u64 init = pk(b1[o], 0.0f);
#pragma unroll
        for (int j = 0; j < 8; j++) acc[j] = init;
        for (int k = 0; k < 128; k += 4) {
            float w0 = W1[(k + 0) * 128 + o];
            float w1 = W1[(k + 1) * 128 + o];
            float w2 = W1[(k + 2) * 128 + o];
            float w3 = W1[(k + 3) * 128 + o];
            u64 wp0 = pk(w0, w1), wp1 = pk(w2, w3);
#pragma unroll
            for (int j = 0; j < 8; j++) {
                float4 s = *(const float4*)&s_in[g * 8 + j][k];
                acc[j] = f2fma(pk(s.x, s.y), wp0, acc[j]);
                acc[j] = f2fma(pk(s.z, s.w), wp1, acc[j]);
            }
        }
#pragma unroll
        for (int j = 0; j < 8; j++) t[g * 8 + j][o] = silu_f(hsum(acc[j]));
    }
    __syncthreads();

    // GEMM2: sj = t @ W3 + b3  (three column slabs per thread)
    {
        u64 a2[8][3];
#pragma unroll
        for (int p = 0; p < 3; p++) {
            u64 init = pk(b3[o + 128 * p], 0.0f);
#pragma unroll
            for (int j = 0; j < 8; j++) a2[j][p] = init;
        }
        for (int k = 0; k < 128; k += 4) {
            u64 wp[3][2];
#pragma unroll
            for (int p = 0; p < 3; p++) {
                float w0 = W3[(k + 0) * 384 + o + 128 * p];
                float w1 = W3[(k + 1) * 384 + o + 128 * p];
                float w2 = W3[(k + 2) * 384 + o + 128 * p];
                float w3 = W3[(k + 3) * 384 + o + 128 * p];
                wp[p][0] = pk(w0, w1);
                wp[p][1] = pk(w2, w3);
            }
#pragma unroll
            for (int j = 0; j < 8; j++) {
                float4 tv = *(const float4*)&t[g * 8 + j][k];
                u64 t01 = pk(tv.x, tv.y), t23 = pk(tv.z, tv.w);
#pragma unroll
                for (int p = 0; p < 3; p++) {
                    a2[j][p] = f2fma(t01, wp[p][0], a2[j][p]);
                    a2[j][p] = f2fma(t23, wp[p][1], a2[j][p]);
                }
            }
        }
#pragma unroll
        for (int j = 0; j < 8; j++) {
            size_t base = (size_t)(nb + g * 8 + j) * 384;
#pragma unroll
            for (int p = 0; p < 3; p++) g_sj[base + o + 128 * p] = hsum(a2[j][p]);
        }
    }
}

// ---------------------------------------------------------------------------
// Kernel B: per-edge phase-1 message + scatter.
// 20 edges/block, 256 threads. W2 slice cached as 30 packed u64 regs/thread.
// ---------------------------------------------------------------------------
__global__ __launch_bounds__(256) void kB(const float* __restrict__ x,
                                          const int* __restrict__ ei,
                                          const float* __restrict__ ea1,
                                          const float* __restrict__ ea2,
                                          const float* __restrict__ W2,
                                          const float* __restrict__ b2,
                                          float* __restrict__ out) {
    __shared__ __align__(16) float split[20][384];   // 30 KB
    __shared__ __align__(8)  float rbfc[20][20];
    __shared__ float ea[20][3];
    __shared__ int   srcs[20], dsts[20];

    const int tid = threadIdx.x;
    const int e0  = blockIdx.x * 20;

    if (tid < 20) {
        srcs[tid] = ei[e0 + tid];
        dsts[tid] = ei[N_EDGES + e0 + tid];
    }
    if (tid >= 32 && tid < 92) {
        int q = tid - 32;
        int e = q / 3, k = q % 3;
        ea[e][k] = ea1[(size_t)(e0 + e) * 3 + k];
    }
    for (int q = tid; q < 400; q += 256) {
        int e = q / 20, n = q % 20;
        float r  = ea2[e0 + e];
        float rb = sqrtf(2.0f / RCUT) * sinpif((float)(n + 1) * r / RCUT) / r;
        float co = 0.5f * (cospif(r / RCUT) + 1.0f) * (r < RCUT ? 1.0f : 0.0f);
        rbfc[e][n] = rb * co;
    }

    const int g = tid >> 7;
    const int o = tid & 127;

    // Packed register-cached W2 slice for this thread's output column
    u64 w2p0[10], w2p1[10], w2p2[10];
#pragma unroll
    for (int n = 0; n < 10; n++) {
        w2p0[n] = pk(W2[(2 * n) * 384 + o],       W2[(2 * n + 1) * 384 + o]);
        w2p1[n] = pk(W2[(2 * n) * 384 + o + 128], W2[(2 * n + 1) * 384 + o + 128]);
        w2p2[n] = pk(W2[(2 * n) * 384 + o + 256], W2[(2 * n + 1) * 384 + o + 256]);
    }
    const u64 b2p0 = pk(b2[o], 0.0f);
    const u64 b2p1 = pk(b2[o + 128], 0.0f);
    const u64 b2p2 = pk(b2[o + 256], 0.0f);
    __syncthreads();

    // Pass 1: split = s_j[src] * (rbfc @ W2 + b2)
#pragma unroll
    for (int el = 0; el < 10; el++) {
        int e = g * 10 + el;
        u64 a0 = b2p0, a1 = b2p1, a2v = b2p2;
#pragma unroll
        for (int n = 0; n < 10; n++) {
            float2 rp = *(const float2*)&rbfc[e][2 * n];
            u64 r = pk(rp.x, rp.y);
            a0  = f2fma(r, w2p0[n], a0);
            a1  = f2fma(r, w2p1[n], a1);
            a2v = f2fma(r, w2p2[n], a2v);
        }
        const float* sjr = g_sj + (size_t)srcs[e] * 384;
        split[e][o]       = hsum(a0)  * sjr[o];
        split[e][o + 128] = hsum(a1)  * sjr[o + 128];
        split[e][o + 256] = hsum(a2v) * sjr[o + 256];
    }
    __syncthreads();

    // Pass 2: msg[3i+k] = x[src,3i+k]*s1[i] + s3[i]*ea1[k]; msg[384+i] = s2[i]
#pragma unroll
    for (int el = 0; el < 10; el++) {
        int e   = g * 10 + el;
        int src = srcs[e], dst = dsts[e];
        float v0, v1, v2, v3;
        if (o < 96) {
            int j0 = 4 * o;
            const float4 xv = *(const float4*)(x + (size_t)src * 512 + j0);
            float xs[4] = {xv.x, xv.y, xv.z, xv.w};
            float vals[4];
#pragma unroll
            for (int tq = 0; tq < 4; tq++) {
                int j = j0 + tq;
                int i = j / 3;
                int k = j - 3 * i;
                vals[tq] = xs[tq] * split[e][i] + split[e][256 + i] * ea[e][k];
            }
            v0 = vals[0]; v1 = vals[1]; v2 = vals[2]; v3 = vals[3];
        } else {
            int i0 = 4 * (o - 96);
            v0 = split[e][128 + i0];
            v1 = split[e][128 + i0 + 1];
            v2 = split[e][128 + i0 + 2];
            v3 = split[e][128 + i0 + 3];
        }
        red4(out + (size_t)dst * 512 + 4 * o, v0, v1, v2, v3);
    }
}

// ---------------------------------------------------------------------------
// Kernel C: per-node phase-2 message into g_msg2. 8 nodes/block, 256 threads.
// ---------------------------------------------------------------------------
__global__ __launch_bounds__(256) void kC(const float* __restrict__ xmid,
                                          const float* __restrict__ U,
                                          const float* __restrict__ V,
                                          const float* __restrict__ Wu1,
                                          const float* __restrict__ bu1,
                                          const float* __restrict__ Wu2,
                                          const float* __restrict__ bu2) {
    __shared__ __align__(16) float vA[8][384];   // v, later overwritten by vV
    __shared__ __align__(16) float vUs[8][384];  // v @ U
    __shared__ __align__(16) float ns[8][256];   // [norm | s]
    __shared__ __align__(16) float h1[8][128];
    __shared__ __align__(16) float h[8][384];

    const int tid = threadIdx.x;
    const int nb  = blockIdx.x * 8;

    for (int idx = tid; idx < 8 * 96; idx += 256) {
        int m = idx / 96, j = (idx % 96) * 4;
        *(float4*)&vA[m][j] = *(const float4*)(xmid + (size_t)(nb + m) * 512 + j);
    }
    for (int idx = tid; idx < 8 * 32; idx += 256) {
        int m = idx >> 5, i = (idx & 31) * 4;
        *(float4*)&ns[m][128 + i] = *(const float4*)(xmid + (size_t)(nb + m) * 512 + 384 + i);
    }
    __syncthreads();

    const int g = tid >> 7;   // 0..1 (4 nodes each)
    const int o = tid & 127;

    // vU = v @ U   (v[a,k] = vA[m][a*128+k])
    {
        u64 acc[4][3];
#pragma unroll
        for (int j = 0; j < 4; j++)
#pragma unroll
            for (int a = 0; a < 3; a++) acc[j][a] = 0ULL;
        for (int k = 0; k < 128; k += 4) {
            float u0 = U[(k + 0) * 128 + o];
            float u1 = U[(k + 1) * 128 + o];
            float u2 = U[(k + 2) * 128 + o];
            float u3 = U[(k + 3) * 128 + o];
            u64 wp0 = pk(u0, u1), wp1 = pk(u2, u3);
#pragma unroll
            for (int j = 0; j < 4; j++) {
                int m = g * 4 + j;
#pragma unroll
                for (int a = 0; a < 3; a++) {
                    float4 s = *(const float4*)&vA[m][a * 128 + k];
                    acc[j][a] = f2fma(pk(s.x, s.y), wp0, acc[j][a]);
                    acc[j][a] = f2fma(pk(s.z, s.w), wp1, acc[j][a]);
                }
            }
        }
#pragma unroll
        for (int j = 0; j < 4; j++)
#pragma unroll
            for (int a = 0; a < 3; a++) vUs[g * 4 + j][a * 128 + o] = hsum(acc[j][a]);
    }
    __syncthreads();

    // vV = vU @ V  -> overwrite vA
    {
        u64 acc[4][3];
#pragma unroll
        for (int j = 0; j < 4; j++)
#pragma unroll
            for (int a = 0; a < 3; a++) acc[j][a] = 0ULL;
        for (int k = 0; k < 128; k += 4) {
            float u0 = V[(k + 0) * 128 + o];
            float u1 = V[(k + 1) * 128 + o];
            float u2 = V[(k + 2) * 128 + o];
            float u3 = V[(k + 3) * 128 + o];
            u64 wp0 = pk(u0, u1), wp1 = pk(u2, u3);
#pragma unroll
            for (int j = 0; j < 4; j++) {
                int m = g * 4 + j;
#pragma unroll
                for (int a = 0; a < 3; a++) {
                    float4 s = *(const float4*)&vUs[m][a * 128 + k];
                    acc[j][a] = f2fma(pk(s.x, s.y), wp0, acc[j][a]);
                    acc[j][a] = f2fma(pk(s.z, s.w), wp1, acc[j][a]);
                }
            }
        }
        __syncthreads();
#pragma unroll
        for (int j = 0; j < 4; j++)
#pragma unroll
            for (int a = 0; a < 3; a++) vA[g * 4 + j][a * 128 + o] = hsum(acc[j][a]);
    }
    __syncthreads();

    // norms
    for (int idx = tid; idx < 8 * 128; idx += 256) {
        int m = idx >> 7, i = idx & 127;
        float x0 = vA[m][3 * i], x1 = vA[m][3 * i + 1], x2 = vA[m][3 * i + 2];
        ns[m][i] = sqrtf(x0 * x0 + x1 * x1 + x2 * x2);
    }
    __syncthreads();

    // h1 = silu([norm|s] @ Wu1 + bu1)
    {
        u64 acc[4];
        u64 init = pk(bu1[o], 0.0f);
#pragma unroll
        for (int j = 0; j < 4; j++) acc[j] = init;
        for (int k = 0; k < 256; k += 4) {
            float w0 = Wu1[(k + 0) * 128 + o];
            float w1 = Wu1[(k + 1) * 128 + o];
            float w2 = Wu1[(k + 2) * 128 + o];
            float w3 = Wu1[(k + 3) * 128 + o];
            u64 wp0 = pk(w0, w1), wp1 = pk(w2, w3);
#pragma unroll
            for (int j = 0; j < 4; j++) {
                float4 s = *(const float4*)&ns[g * 4 + j][k];
                acc[j] = f2fma(pk(s.x, s.y), wp0, acc[j]);
                acc[j] = f2fma(pk(s.z, s.w), wp1, acc[j]);
            }
        }
#pragma unroll
        for (int j = 0; j < 4; j++) h1[g * 4 + j][o] = silu_f(hsum(acc[j]));
    }
    __syncthreads();

    // h = h1 @ Wu2 + bu2
    {
        u64 acc[4][3];
#pragma unroll
        for (int p = 0; p < 3; p++) {
            u64 init = pk(bu2[o + 128 * p], 0.0f);
#pragma unroll
            for (int j = 0; j < 4; j++) acc[j][p] = init;
        }
        for (int k = 0; k < 128; k += 4) {
            u64 wp[3][2];
#pragma unroll
            for (int p = 0; p < 3; p++) {
                float w0 = Wu2[(k + 0) * 384 + o + 128 * p];
                float w1 = Wu2[(k + 1) * 384 + o + 128 * p];
                float w2 = Wu2[(k + 2) * 384 + o + 128 * p];
                float w3 = Wu2[(k + 3) * 384 + o + 128 * p];
                wp[p][0] = pk(w0, w1);
                wp[p][1] = pk(w2, w3);
            }
#pragma unroll
            for (int j = 0; j < 4; j++) {
                float4 tv = *(const float4*)&h1[g * 4 + j][k];
                u64 t01 = pk(tv.x, tv.y), t23 = pk(tv.z, tv.w);
#pragma unroll
                for (int p = 0; p < 3; p++) {
                    acc[j][p] = f2fma(t01, wp[p][0], acc[j][p]);
                    acc[j][p] = f2fma(t23, wp[p][1], acc[j][p]);
                }
            }
        }
#pragma unroll
        for (int j = 0; j < 4; j++)
#pragma unroll
            for (int p = 0; p < 3; p++) h[g * 4 + j][o + 128 * p] = hsum(acc[j][p]);
    }
    __syncthreads();

    // msg2
    for (int idx = tid; idx < 8 * 512; idx += 256) {
        int m = idx >> 9, j = idx & 511;
        float val;
        if (j < 384) {
            val = vUs[m][j] * h[m][j / 3];
        } else {
            int i = j - 384;
            float d = vUs[m][3 * i]     * vA[m][3 * i]
                    + vUs[m][3 * i + 1] * vA[m][3 * i + 1]
                    + vUs[m][3 * i + 2] * vA[m][3 * i + 2];
            val = d * h[m][i] + h[m][256 + i];
        }
        g_msg2[(size_t)(nb + m) * 512 + j] = val;
    }
}

// ---------------------------------------------------------------------------
// Kernel D: per-edge scatter of the per-node phase-2 message.
// 4 edges/block, 256 threads, 2 edges per thread (MLP=2).
// ---------------------------------------------------------------------------
__global__ __launch_bounds__(256) void kD(const int* __restrict__ ei,
                                          float* __restrict__ out) {
    const int tid = threadIdx.x;
    const int g = tid >> 7, o = tid & 127;
    const int e0 = blockIdx.x * 4 + g * 2;

    const int src0 = ei[e0],     dst0 = ei[N_EDGES + e0];
    const int src1 = ei[e0 + 1], dst1 = ei[N_EDGES + e0 + 1];
    const float4 v0 = *(const float4*)(g_msg2 + (size_t)src0 * 512 + 4 * o);
    const float4 v1 = *(const float4*)(g_msg2 + (size_t)src1 * 512 + 4 * o);
    red4(out + (size_t)dst0 * 512 + 4 * o, v0.x, v0.y, v0.z, v0.w);
    red4(out + (size_t)dst1 * 512 + 4 * o, v1.x, v1.y, v1.z, v1.w);
}

// ---------------------------------------------------------------------------
extern "C" void kernel_launch(void* const* d_in, const int* in_sizes, int n_in,
                              void* d_out, int out_size) {
    const float* x   = (const float*)d_in[0];
    const int*   ei  = (const int*)d_in[1];     // int32 (jax x64 disabled)
    const float* ea1 = (const float*)d_in[2];
    const float* ea2 = (const float*)d_in[3];
    const float* W1  = (const float*)d_in[4];
    const float* b1  = (const float*)d_in[5];
    const float* W2  = (const float*)d_in[6];
    const float* b2  = (const float*)d_in[7];
    const float* W3  = (const float*)d_in[8];
    const float* b3  = (const float*)d_in[9];
    const float* U   = (const float*)d_in[10];
    const float* V   = (const float*)d_in[11];
    const float* Wu1 = (const float*)d_in[12];
    const float* bu1 = (const float*)d_in[13];
    const float* Wu2 = (const float*)d_in[14];
    const float* bu2 = (const float*)d_in[15];
    float* out = (float*)d_out;

    cudaMemcpyAsync(out, x, (size_t)N_NODES * 512 * sizeof(float),
                    cudaMemcpyDeviceToDevice);

    kA<<<N_NODES / 16, 256>>>(x, W1, b1, W3, b3);
    kB<<<N_EDGES / 20, 256>>>(x, ei, ea1, ea2, W2, b2, out);
    kC<<<N_NODES / 8, 256>>>(out, U, V, Wu1, bu1, Wu2, bu2);
    kD<<<N_EDGES / 4, 256>>>(ei, out);
}